// round 8
// baseline (speedup 1.0000x reference)
#include <cuda_runtime.h>
#include <cuda_bf16.h>

// Problem constants
#define B_DIM 16
#define T_DIM 100
#define FRAME_INTS 3888         // 27*48*3
#define NBINS 512
#define WIN 101
#define HALF 50
#define ODIM 128

// Scratch (device globals — no allocation allowed)
__device__ float g_hist[B_DIM * T_DIM * NBINS];   // 3.28 MB
__device__ float g_sim [B_DIM * T_DIM * T_DIM];   // 640 KB

// ---- f32x2 packed-FMA helpers (FFMA2) --------------------------------------
__device__ __forceinline__ void ffma2(unsigned long long& d,
                                      unsigned long long a,
                                      unsigned long long b) {
    asm("fma.rn.f32x2 %0, %1, %2, %0;" : "+l"(d) : "l"(a), "l"(b));
}
__device__ __forceinline__ float2 f2unpack(unsigned long long u) {
    float2 f;
    asm("mov.b64 {%0, %1}, %2;" : "=f"(f.x), "=f"(f.y) : "l"(u));
    return f;
}
__device__ __forceinline__ unsigned long long f2pack(float a, float b) {
    unsigned long long u;
    asm("mov.b64 %0, {%1, %2};" : "=l"(u) : "f"(a), "f"(b));
    return u;
}

// ---------------------------------------------------------------------------
// Kernel 1: per-frame 512-bin color histogram + L2 normalize.
// Pinned at the smem-ATOMS floor (~2.07M atomics / 148 SMs) — R5 version.
// ---------------------------------------------------------------------------
__global__ __launch_bounds__(256) void k_hist(const int* __restrict__ frames,
                                              float* __restrict__ hist) {
    __shared__ int sh[NBINS];
    __shared__ int wsum[8];
    __shared__ float s_inv;

    const int f   = blockIdx.x;
    const int tid = threadIdx.x;

    for (int i = tid; i < NBINS; i += 256) sh[i] = 0;
    __syncthreads();

    const int4* base = reinterpret_cast<const int4*>(frames + (long long)f * FRAME_INTS);
    for (int c = tid; c < 324; c += 256) {
        int4 a = base[3*c+0];
        int4 b = base[3*c+1];
        int4 d = base[3*c+2];
        atomicAdd(&sh[((a.x >> 5) << 6) | ((a.y >> 5) << 3) | (a.z >> 5)], 1);
        atomicAdd(&sh[((a.w >> 5) << 6) | ((b.x >> 5) << 3) | (b.y >> 5)], 1);
        atomicAdd(&sh[((b.z >> 5) << 6) | ((b.w >> 5) << 3) | (d.x >> 5)], 1);
        atomicAdd(&sh[((d.y >> 5) << 6) | ((d.z >> 5) << 3) | (d.w >> 5)], 1);
    }
    __syncthreads();

    int local = 0;
    for (int i = tid; i < NBINS; i += 256) { int h = sh[i]; local += h * h; }
    #pragma unroll
    for (int o = 16; o; o >>= 1) local += __shfl_down_sync(0xffffffff, local, o);
    if ((tid & 31) == 0) wsum[tid >> 5] = local;
    __syncthreads();
    if (tid == 0) {
        int tot = 0;
        #pragma unroll
        for (int w = 0; w < 8; w++) tot += wsum[w];
        s_inv = 1.0f / sqrtf((float)tot);
    }
    __syncthreads();

    const float inv = s_inv;
    float* out = hist + (long long)f * NBINS;
    for (int i = tid; i < NBINS; i += 256) out[i] = (float)sh[i] * inv;
}

// ---------------------------------------------------------------------------
// Kernel 2: sim[b] = X[b] @ X[b]^T, banded + symmetric.
// 32x32x512 smem-resident tile, 512 threads, 2 barriers.
// Thread tiling 4x4 with mod-8 row/col spacing: rows tr+8i, cols tc+8j.
// -> every LDS.128 is conflict-free AND broadcast-heavy (A: 4 distinct
// addrs/warp, B: 8 distinct). 8-way k-split (kq = tid>>6, 64 k each).
// ---------------------------------------------------------------------------
__constant__ int c_ti[9] = {0,0,0,1,1,1,2,2,3};
__constant__ int c_tj[9] = {0,1,2,1,2,3,2,3,3};

#define AS_STRIDE 516
#define RED_FLOATS (8*32*36)
#define SIM_SMEM_FLOATS (2*32*AS_STRIDE + RED_FLOATS)
#define SIM_SMEM_BYTES  (SIM_SMEM_FLOATS * 4)       // 168,960 B

__global__ __launch_bounds__(512) void k_sim(const float* __restrict__ hist,
                                             float* __restrict__ sim) {
    extern __shared__ __align__(16) float sm[];
    float* A_s = sm;                          // [32][516]
    float* B_s = sm + 32 * AS_STRIDE;         // [32][516]
    float* red = sm + 64 * AS_STRIDE;         // [8][32][36]

    const int b  = blockIdx.y;
    const int tl = blockIdx.x;
    const int ti = c_ti[tl], tj = c_tj[tl];
    const bool diag = (ti == tj);

    const int row0 = ti * 32;
    const int col0 = tj * 32;
    const float* X = hist + (long long)b * T_DIM * NBINS;
    const int tid = threadIdx.x;

    // Load tiles (float4 coalesced, zero-fill rows >= 100)
    for (int i = tid; i < 4096; i += 512) {
        int row = i >> 7;
        int k   = (i & 127) << 2;
        float4 va = make_float4(0.f, 0.f, 0.f, 0.f);
        int gr = row0 + row;
        if (gr < T_DIM) va = *reinterpret_cast<const float4*>(X + gr * NBINS + k);
        *reinterpret_cast<float4*>(A_s + row * AS_STRIDE + k) = va;
        if (!diag) {
            float4 vb = make_float4(0.f, 0.f, 0.f, 0.f);
            int gc = col0 + row;
            if (gc < T_DIM) vb = *reinterpret_cast<const float4*>(X + gc * NBINS + k);
            *reinterpret_cast<float4*>(B_s + row * AS_STRIDE + k) = vb;
        }
    }
    __syncthreads();

    const float* Bp = diag ? A_s : B_s;
    const int kq = tid >> 6;          // k-quarter: k in [64kq, 64kq+64)
    const int g  = tid & 63;
    const int tr = g >> 3;            // rows tr, tr+8, tr+16, tr+24
    const int tc = g & 7;             // cols tc, tc+8, tc+16, tc+24
    const int kb = 64 * kq;

    unsigned long long acc[4][4];
    #pragma unroll
    for (int i = 0; i < 4; i++)
        #pragma unroll
        for (int j = 0; j < 4; j++) acc[i][j] = 0ull;

    const float* aP = A_s + tr * AS_STRIDE + kb;
    const float* bP = Bp  + tc * AS_STRIDE + kb;

    #pragma unroll 4
    for (int kk = 0; kk < 64; kk += 4) {
        ulonglong2 av[4], bv[4];
        #pragma unroll
        for (int i = 0; i < 4; i++)
            av[i] = *reinterpret_cast<const ulonglong2*>(aP + i * 8 * AS_STRIDE + kk);
        #pragma unroll
        for (int j = 0; j < 4; j++)
            bv[j] = *reinterpret_cast<const ulonglong2*>(bP + j * 8 * AS_STRIDE + kk);

        // 16 FFMA2 on .x then 16 on .y: dep distance 16 per accumulator
        #pragma unroll
        for (int i = 0; i < 4; i++)
            #pragma unroll
            for (int j = 0; j < 4; j++) ffma2(acc[i][j], av[i].x, bv[j].x);
        #pragma unroll
        for (int i = 0; i < 4; i++)
            #pragma unroll
            for (int j = 0; j < 4; j++) ffma2(acc[i][j], av[i].y, bv[j].y);
    }

    // Partial sums per k-quarter
    float* redq = red + kq * (32 * 36);
    #pragma unroll
    for (int i = 0; i < 4; i++) {
        #pragma unroll
        for (int j = 0; j < 4; j++) {
            float2 f = f2unpack(acc[i][j]);
            redq[(tr + 8*i) * 36 + (tc + 8*j)] = f.x + f.y;
        }
    }
    __syncthreads();

    // Combine 8 partials + write with symmetry (2 outputs per thread)
    float* S = sim + (long long)b * T_DIM * T_DIM;
    #pragma unroll
    for (int u = 0; u < 2; u++) {
        int o = tid + u * 512;
        int r = o >> 5, c = o & 31;
        float v = 0.f;
        #pragma unroll
        for (int q = 0; q < 8; q++) v += red[q * (32*36) + r * 36 + c];
        int gr = row0 + r, gc = col0 + c;
        if (gr < T_DIM && gc < T_DIM) {
            S[gr * T_DIM + gc] = v;
            S[gc * T_DIM + gr] = v;
        }
    }
}

// ---------------------------------------------------------------------------
// Kernel 3: band extraction + FC + ReLU (R5 version).
// 256 threads: tid = d + 128*h; h=0 s in [0,52), h=1 s in [52,101).
// Band transposed [s][tt] -> per j: 3 vector broadcasts + 5 FFMA2.
// ---------------------------------------------------------------------------
#define FC_W_FLOATS  (WIN * ODIM)             // 12928
#define FC_BT_OFF    FC_W_FLOATS
#define FC_SCR_OFF   (FC_W_FLOATS + 104 * 12)
#define FC_SMEM_FLOATS (FC_SCR_OFF + 10 * ODIM)
#define FC_SMEM_BYTES  (FC_SMEM_FLOATS * 4)

__global__ __launch_bounds__(256) void k_fc(const float* __restrict__ sim,
                                            const float* __restrict__ fc_w,
                                            const float* __restrict__ fc_b,
                                            float* __restrict__ out) {
    extern __shared__ __align__(16) float dyn[];
    float* w_s    = dyn;                 // [101][128]
    float* band_t = dyn + FC_BT_OFF;     // [s][12]
    float* scr    = dyn + FC_SCR_OFF;    // [10][128]

    const int b   = blockIdx.y;
    const int t0  = blockIdx.x * 10;
    const int tid = threadIdx.x;
    const int d   = tid & 127;
    const int h   = tid >> 7;

    {
        const float4* src = reinterpret_cast<const float4*>(fc_w);
        float4* dst = reinterpret_cast<float4*>(w_s);
        for (int i = tid; i < FC_W_FLOATS / 4; i += 256) dst[i] = src[i];
    }

    const float* S = sim + (long long)b * T_DIM * T_DIM;
    for (int i = tid; i < 10 * WIN; i += 256) {
        int tt = i / WIN, s = i - tt * WIN;
        int t  = t0 + tt;
        int t2 = t + s - HALF;
        band_t[s * 12 + tt] = (t2 >= 0 && t2 < T_DIM) ? S[t * T_DIM + t2] : 0.f;
    }
    __syncthreads();

    const int s0 = h ? 52 : 0;
    const int ns = h ? 49 : 52;

    unsigned long long acc2[5];
    #pragma unroll
    for (int i = 0; i < 5; i++) acc2[i] = 0ull;

    const float* wp = w_s + d;
    for (int j = 0; j < ns; j++) {
        const int s = s0 + j;
        float wv = wp[s * ODIM];
        unsigned long long ww = f2pack(wv, wv);
        const float* bt = band_t + s * 12;
        ulonglong2 p01 = *reinterpret_cast<const ulonglong2*>(bt);
        ulonglong2 p23 = *reinterpret_cast<const ulonglong2*>(bt + 4);
        unsigned long long p4 = *reinterpret_cast<const unsigned long long*>(bt + 8);
        ffma2(acc2[0], ww, p01.x);
        ffma2(acc2[1], ww, p01.y);
        ffma2(acc2[2], ww, p23.x);
        ffma2(acc2[3], ww, p23.y);
        ffma2(acc2[4], ww, p4);
    }

    float acc[10];
    #pragma unroll
    for (int p = 0; p < 5; p++) {
        float2 f = f2unpack(acc2[p]);
        acc[2 * p]     = f.x;
        acc[2 * p + 1] = f.y;
    }

    if (h == 1) {
        #pragma unroll
        for (int tt = 0; tt < 10; tt++) scr[tt * ODIM + d] = acc[tt];
    }
    __syncthreads();

    if (h == 0) {
        const float bias = fc_b[d];
        float* O = out + ((long long)(b * T_DIM + t0)) * ODIM + d;
        #pragma unroll
        for (int tt = 0; tt < 10; tt++) {
            float v = acc[tt] + scr[tt * ODIM + d] + bias;
            O[tt * ODIM] = fmaxf(v, 0.f);
        }
    }
}

// ---------------------------------------------------------------------------
extern "C" void kernel_launch(void* const* d_in, const int* in_sizes, int n_in,
                              void* d_out, int out_size) {
    const int*   frames = (const int*)  d_in[0];
    const float* fc_w   = (const float*)d_in[1];
    const float* fc_b   = (const float*)d_in[2];
    float*       out    = (float*)d_out;

    float* hist;
    float* sim;
    cudaGetSymbolAddress((void**)&hist, g_hist);
    cudaGetSymbolAddress((void**)&sim,  g_sim);

    cudaFuncSetAttribute(k_sim, cudaFuncAttributeMaxDynamicSharedMemorySize,
                         SIM_SMEM_BYTES);
    cudaFuncSetAttribute(k_fc, cudaFuncAttributeMaxDynamicSharedMemorySize,
                         FC_SMEM_BYTES);

    k_hist<<<B_DIM * T_DIM, 256>>>(frames, hist);
    k_sim <<<dim3(9, B_DIM), 512, SIM_SMEM_BYTES>>>(hist, sim);
    k_fc  <<<dim3(T_DIM / 10, B_DIM), 256, FC_SMEM_BYTES>>>(sim, fc_w, fc_b, out);
}

// round 9
// speedup vs baseline: 1.1047x; 1.1047x over previous
#include <cuda_runtime.h>
#include <cuda_bf16.h>

// Problem constants
#define B_DIM 16
#define T_DIM 100
#define FRAME_INTS 3888         // 27*48*3
#define NBINS 512
#define WIN 101
#define HALF 50
#define ODIM 128

// Scratch (device globals — no allocation allowed)
__device__ float g_hist[B_DIM * T_DIM * NBINS];   // 3.28 MB
__device__ float g_sim [B_DIM * T_DIM * T_DIM];   // 640 KB

// ---- f32x2 packed-FMA helpers (FFMA2) --------------------------------------
__device__ __forceinline__ void ffma2(unsigned long long& d,
                                      unsigned long long a,
                                      unsigned long long b) {
    asm("fma.rn.f32x2 %0, %1, %2, %0;" : "+l"(d) : "l"(a), "l"(b));
}
__device__ __forceinline__ float2 f2unpack(unsigned long long u) {
    float2 f;
    asm("mov.b64 {%0, %1}, %2;" : "=f"(f.x), "=f"(f.y) : "l"(u));
    return f;
}
__device__ __forceinline__ unsigned long long f2pack(float a, float b) {
    unsigned long long u;
    asm("mov.b64 %0, {%1, %2};" : "=l"(u) : "f"(a), "f"(b));
    return u;
}

// ---------------------------------------------------------------------------
// Kernel 1: per-frame 512-bin color histogram + L2 normalize.
// Pinned at the smem-ATOMS floor (~2.07M atomics / 148 SMs) — R5 version.
// ---------------------------------------------------------------------------
__global__ __launch_bounds__(256) void k_hist(const int* __restrict__ frames,
                                              float* __restrict__ hist) {
    __shared__ int sh[NBINS];
    __shared__ int wsum[8];
    __shared__ float s_inv;

    const int f   = blockIdx.x;
    const int tid = threadIdx.x;

    for (int i = tid; i < NBINS; i += 256) sh[i] = 0;
    __syncthreads();

    const int4* base = reinterpret_cast<const int4*>(frames + (long long)f * FRAME_INTS);
    for (int c = tid; c < 324; c += 256) {
        int4 a = base[3*c+0];
        int4 b = base[3*c+1];
        int4 d = base[3*c+2];
        atomicAdd(&sh[((a.x >> 5) << 6) | ((a.y >> 5) << 3) | (a.z >> 5)], 1);
        atomicAdd(&sh[((a.w >> 5) << 6) | ((b.x >> 5) << 3) | (b.y >> 5)], 1);
        atomicAdd(&sh[((b.z >> 5) << 6) | ((b.w >> 5) << 3) | (d.x >> 5)], 1);
        atomicAdd(&sh[((d.y >> 5) << 6) | ((d.z >> 5) << 3) | (d.w >> 5)], 1);
    }
    __syncthreads();

    int local = 0;
    for (int i = tid; i < NBINS; i += 256) { int h = sh[i]; local += h * h; }
    #pragma unroll
    for (int o = 16; o; o >>= 1) local += __shfl_down_sync(0xffffffff, local, o);
    if ((tid & 31) == 0) wsum[tid >> 5] = local;
    __syncthreads();
    if (tid == 0) {
        int tot = 0;
        #pragma unroll
        for (int w = 0; w < 8; w++) tot += wsum[w];
        s_inv = 1.0f / sqrtf((float)tot);
    }
    __syncthreads();

    const float inv = s_inv;
    float* out = hist + (long long)f * NBINS;
    for (int i = tid; i < NBINS; i += 256) out[i] = (float)sh[i] * inv;
}

// ---------------------------------------------------------------------------
// Kernel 2: sim[b] = X[b] @ X[b]^T, banded + symmetric.
// R5's exact thread mapping / accumulator scheme (16 warps = 4 k-quarters x
// 4 col-groups; FFMA2), but fed in four k=128 chunks with register prefetch
// + double-buffered smem so LDGs overlap compute. Diag tiles alias A==B.
// ---------------------------------------------------------------------------
__constant__ int c_ti[9] = {0,0,0,1,1,1,2,2,3};
__constant__ int c_tj[9] = {0,1,2,1,2,3,2,3,3};

#define CH_STRIDE 132                              // 128 + 4 pad
#define SIM_SMEM_FLOATS (2*2*32*CH_STRIDE + 4*32*36)
#define SIM_SMEM_BYTES  (SIM_SMEM_FLOATS * 4)      // 86016 B

__global__ __launch_bounds__(512) void k_sim(const float* __restrict__ hist,
                                             float* __restrict__ sim) {
    extern __shared__ __align__(16) float sm[];
    float* A_s = sm;                               // [2][32][132]
    float* B_s = sm + 2 * 32 * CH_STRIDE;          // [2][32][132]
    float* red = sm + 4 * 32 * CH_STRIDE;          // [4][32][36]

    const int b  = blockIdx.y;
    const int tl = blockIdx.x;
    const int ti = c_ti[tl], tj = c_tj[tl];
    const bool diag = (ti == tj);

    const int row0 = ti * 32;
    const int col0 = tj * 32;
    const float* X = hist + (long long)b * T_DIM * NBINS;
    const int tid = threadIdx.x;

    // Two load slots per thread per tile: idx = tid, tid+512.
    // rowj = idx>>5 (0..31), colj = (idx&31)*4. Clamp OOB rows to 99
    // (garbage lands in rows masked at write).
    const float* pa[2];
    const float* pb[2];
    int   srow[2];
    int   scol[2];
    #pragma unroll
    for (int j = 0; j < 2; j++) {
        int idx = tid + j * 512;
        srow[j] = idx >> 5;
        scol[j] = (idx & 31) << 2;
        pa[j] = X + min(row0 + srow[j], T_DIM - 1) * NBINS + scol[j];
        pb[j] = X + min(col0 + srow[j], T_DIM - 1) * NBINS + scol[j];
    }

    // Prime chunk 0
    float4 ra[2], rb[2];
    #pragma unroll
    for (int j = 0; j < 2; j++) {
        ra[j] = *reinterpret_cast<const float4*>(pa[j]);
        if (!diag) rb[j] = *reinterpret_cast<const float4*>(pb[j]);
    }
    #pragma unroll
    for (int j = 0; j < 2; j++) {
        *reinterpret_cast<float4*>(A_s + srow[j] * CH_STRIDE + scol[j]) = ra[j];
        if (!diag)
            *reinterpret_cast<float4*>(B_s + srow[j] * CH_STRIDE + scol[j]) = rb[j];
    }
    __syncthreads();

    // Compute mapping (R5): warp w -> (q = k-quarter-within-chunk, wc = col-grp)
    const int w    = tid >> 5;
    const int lane = tid & 31;
    const int q    = w >> 2;          // k in [32q, 32q+32) of each chunk
    const int wc   = w & 3;
    const int r0   = lane & 15;       // rows r0, r0+16
    const int rh   = lane >> 4;
    const int cb   = 8 * wc + 4 * rh; // cols cb..cb+3

    unsigned long long acc[8];
    #pragma unroll
    for (int i = 0; i < 8; i++) acc[i] = 0ull;

    #pragma unroll
    for (int ch = 0; ch < 4; ch++) {
        const int buf = ch & 1;
        float* Ab = A_s + buf * (32 * CH_STRIDE);
        float* Bb = diag ? Ab : (B_s + buf * (32 * CH_STRIDE));

        // Prefetch next chunk into registers (LDGs fly during compute)
        if (ch < 3) {
            const int kc = (ch + 1) * 128;
            #pragma unroll
            for (int j = 0; j < 2; j++) {
                ra[j] = *reinterpret_cast<const float4*>(pa[j] + kc);
                if (!diag) rb[j] = *reinterpret_cast<const float4*>(pb[j] + kc);
            }
        }

        const float* a0 = Ab + r0 * CH_STRIDE + 32 * q;
        const float* a1 = a0 + 16 * CH_STRIDE;
        const float* b0 = Bb + cb * CH_STRIDE + 32 * q;
        const float* b1 = b0 + CH_STRIDE;
        const float* b2 = b1 + CH_STRIDE;
        const float* b3 = b2 + CH_STRIDE;

        #pragma unroll
        for (int k = 0; k < 32; k += 4) {
            ulonglong2 aL = *reinterpret_cast<const ulonglong2*>(a0 + k);
            ulonglong2 aH = *reinterpret_cast<const ulonglong2*>(a1 + k);
            ulonglong2 q0 = *reinterpret_cast<const ulonglong2*>(b0 + k);
            ulonglong2 q1 = *reinterpret_cast<const ulonglong2*>(b1 + k);
            ulonglong2 q2 = *reinterpret_cast<const ulonglong2*>(b2 + k);
            ulonglong2 q3 = *reinterpret_cast<const ulonglong2*>(b3 + k);

            ffma2(acc[0], aL.x, q0.x); ffma2(acc[0], aL.y, q0.y);
            ffma2(acc[1], aL.x, q1.x); ffma2(acc[1], aL.y, q1.y);
            ffma2(acc[2], aL.x, q2.x); ffma2(acc[2], aL.y, q2.y);
            ffma2(acc[3], aL.x, q3.x); ffma2(acc[3], aL.y, q3.y);
            ffma2(acc[4], aH.x, q0.x); ffma2(acc[4], aH.y, q0.y);
            ffma2(acc[5], aH.x, q1.x); ffma2(acc[5], aH.y, q1.y);
            ffma2(acc[6], aH.x, q2.x); ffma2(acc[6], aH.y, q2.y);
            ffma2(acc[7], aH.x, q3.x); ffma2(acc[7], aH.y, q3.y);
        }

        if (ch < 3) {
            __syncthreads();   // all warps done with buf^1 (chunk ch-1)
            const int nb = (ch + 1) & 1;
            float* An = A_s + nb * (32 * CH_STRIDE);
            float* Bn = B_s + nb * (32 * CH_STRIDE);
            #pragma unroll
            for (int j = 0; j < 2; j++) {
                *reinterpret_cast<float4*>(An + srow[j] * CH_STRIDE + scol[j]) = ra[j];
                if (!diag)
                    *reinterpret_cast<float4*>(Bn + srow[j] * CH_STRIDE + scol[j]) = rb[j];
            }
            __syncthreads();   // next chunk ready
        }
    }

    // Partial sums per k-quarter, then combine + write with symmetry
    #pragma unroll
    for (int rr = 0; rr < 2; rr++) {
        #pragma unroll
        for (int cc = 0; cc < 4; cc++) {
            float2 f = f2unpack(acc[rr * 4 + cc]);
            red[(q * 32 + r0 + 16 * rr) * 36 + cb + cc] = f.x + f.y;
        }
    }
    __syncthreads();

    float* S = sim + (long long)b * T_DIM * T_DIM;
    #pragma unroll
    for (int j = 0; j < 2; j++) {
        int o = tid + j * 512;
        int r = o >> 5, c = o & 31;
        float v = red[(r     ) * 36 + c] + red[(32 + r) * 36 + c]
                + red[(64 + r) * 36 + c] + red[(96 + r) * 36 + c];
        int gr = row0 + r, gc = col0 + c;
        if (gr < T_DIM && gc < T_DIM) {
            S[gr * T_DIM + gc] = v;
            S[gc * T_DIM + gr] = v;
        }
    }
}

// ---------------------------------------------------------------------------
// Kernel 3: band extraction + FC + ReLU.
// 512 threads = (d in 128) x (q = s-quarter). Band transposed [s][tt];
// per s: 3 vector broadcasts + pack + 5 FFMA2. smem combine of quarters.
// ---------------------------------------------------------------------------
#define FC_W_FLOATS  (WIN * ODIM)             // 12928
#define FC_BT_OFF    FC_W_FLOATS              // band_t [104][12]
#define FC_SCR_OFF   (FC_W_FLOATS + 104 * 12)
#define FC_SMEM_FLOATS (FC_SCR_OFF + 3 * 10 * ODIM)
#define FC_SMEM_BYTES  (FC_SMEM_FLOATS * 4)

__global__ __launch_bounds__(512) void k_fc(const float* __restrict__ sim,
                                            const float* __restrict__ fc_w,
                                            const float* __restrict__ fc_b,
                                            float* __restrict__ out) {
    extern __shared__ __align__(16) float dyn[];
    float* w_s    = dyn;                 // [101][128]
    float* band_t = dyn + FC_BT_OFF;     // [s][12]
    float* scr    = dyn + FC_SCR_OFF;    // [3][10][128]

    const int b   = blockIdx.y;
    const int t0  = blockIdx.x * 10;
    const int tid = threadIdx.x;
    const int d   = tid & 127;
    const int q   = tid >> 7;

    {
        const float4* src = reinterpret_cast<const float4*>(fc_w);
        float4* dst = reinterpret_cast<float4*>(w_s);
        for (int i = tid; i < FC_W_FLOATS / 4; i += 512) dst[i] = src[i];
    }

    const float* S = sim + (long long)b * T_DIM * T_DIM;
    for (int i = tid; i < 10 * WIN; i += 512) {
        int tt = i / WIN, s = i - tt * WIN;
        int t  = t0 + tt;
        int t2 = t + s - HALF;
        band_t[s * 12 + tt] = (t2 >= 0 && t2 < T_DIM) ? S[t * T_DIM + t2] : 0.f;
    }
    __syncthreads();

    const int s0 = q * 26;
    const int s1 = min(WIN, s0 + 26);

    unsigned long long acc2[5];
    #pragma unroll
    for (int i = 0; i < 5; i++) acc2[i] = 0ull;

    const float* wp = w_s + d;
    for (int s = s0; s < s1; s++) {
        float wv = wp[s * ODIM];
        unsigned long long ww = f2pack(wv, wv);
        const float* bt = band_t + s * 12;
        ulonglong2 p01 = *reinterpret_cast<const ulonglong2*>(bt);
        ulonglong2 p23 = *reinterpret_cast<const ulonglong2*>(bt + 4);
        unsigned long long p4 = *reinterpret_cast<const unsigned long long*>(bt + 8);
        ffma2(acc2[0], ww, p01.x);
        ffma2(acc2[1], ww, p01.y);
        ffma2(acc2[2], ww, p23.x);
        ffma2(acc2[3], ww, p23.y);
        ffma2(acc2[4], ww, p4);
    }

    float acc[10];
    #pragma unroll
    for (int p = 0; p < 5; p++) {
        float2 f = f2unpack(acc2[p]);
        acc[2 * p]     = f.x;
        acc[2 * p + 1] = f.y;
    }

    if (q) {
        float* sc = scr + (q - 1) * (10 * ODIM);
        #pragma unroll
        for (int tt = 0; tt < 10; tt++) sc[tt * ODIM + d] = acc[tt];
    }
    __syncthreads();

    if (q == 0) {
        const float bias = fc_b[d];
        float* O = out + ((long long)(b * T_DIM + t0)) * ODIM + d;
        #pragma unroll
        for (int tt = 0; tt < 10; tt++) {
            float v = acc[tt] + bias
                    + scr[0 * (10*ODIM) + tt * ODIM + d]
                    + scr[1 * (10*ODIM) + tt * ODIM + d]
                    + scr[2 * (10*ODIM) + tt * ODIM + d];
            O[tt * ODIM] = fmaxf(v, 0.f);
        }
    }
}

// ---------------------------------------------------------------------------
extern "C" void kernel_launch(void* const* d_in, const int* in_sizes, int n_in,
                              void* d_out, int out_size) {
    const int*   frames = (const int*)  d_in[0];
    const float* fc_w   = (const float*)d_in[1];
    const float* fc_b   = (const float*)d_in[2];
    float*       out    = (float*)d_out;

    float* hist;
    float* sim;
    cudaGetSymbolAddress((void**)&hist, g_hist);
    cudaGetSymbolAddress((void**)&sim,  g_sim);

    cudaFuncSetAttribute(k_sim, cudaFuncAttributeMaxDynamicSharedMemorySize,
                         SIM_SMEM_BYTES);
    cudaFuncSetAttribute(k_fc, cudaFuncAttributeMaxDynamicSharedMemorySize,
                         FC_SMEM_BYTES);

    k_hist<<<B_DIM * T_DIM, 256>>>(frames, hist);
    k_sim <<<dim3(9, B_DIM), 512, SIM_SMEM_BYTES>>>(hist, sim);
    k_fc  <<<dim3(T_DIM / 10, B_DIM), 512, FC_SMEM_BYTES>>>(sim, fc_w, fc_b, out);
}